// round 11
// baseline (speedup 1.0000x reference)
#include <cuda_runtime.h>
#include <math.h>

#define NW    296
#define XPAD  300           // padded xe row (bank-conflict-free: (12r+4I)%32 distinct)
#define FMD   74
#define NBIN  2701          // 74*73/2
#define NBINP 2816          // 22 * 128 (padded; pad weights stay zero)
#define NBP   (NBINP/2)     // 1408 bin-pairs
#define NCHUNK 22
#define NHEAD 64
#define NEMB  48
#define RB    8             // rows per block
#define SEGS  8
#define SEGLEN ((NBIN + SEGS - 1) / SEGS)   // 338

// __device__ scratch (zero-initialized at module load; pads never written)
__device__ float g_wA2[NBP * 128];          // [bpair][head][2bins], = (wNDI[h,I,J]-wNDI[h,J,I])/16
__device__ float g_wDIeff[FMD * NHEAD];     // (colsum-rowsum)/4, K-major
__device__ unsigned short g_binIJ[NBIN];    // (I<<8)|J

__device__ __forceinline__ float elu1(float v) { return v > 0.f ? v : expm1f(v); }

__device__ __forceinline__ unsigned long long pk2(float a, float b) {
    unsigned long long r;
    asm("mov.b64 %0, {%1, %2};" : "=l"(r) : "f"(a), "f"(b));
    return r;
}
__device__ __forceinline__ void upk2(float& a, float& b, unsigned long long v) {
    asm("mov.b64 {%0, %1}, %2;" : "=f"(a), "=f"(b) : "l"(v));
}
// packed dual-FMA: only reachable via PTX fma.rn.f32x2
__device__ __forceinline__ void ffma2(unsigned long long& d, unsigned long long a, unsigned long long b) {
    asm("fma.rn.f32x2 %0, %1, %2, %0;" : "+l"(d) : "l"(a), "l"(b));
}

// ---------------- prep: build effective weights + LUT ----------------
__global__ __launch_bounds__(256) void prep_kernel(const float* __restrict__ wDI,
                                                   const float* __restrict__ wNDI) {
    __shared__ float w[FMD * FMD];
    int blk = blockIdx.x;
    int tid = threadIdx.x;
    if (blk < NHEAD * SEGS) {
        int h = blk >> 3, seg = blk & (SEGS - 1);
        const float* src = wNDI + h * FMD * FMD;
        for (int i = tid; i < FMD * FMD; i += 256) w[i] = src[i];
        __syncthreads();
        int t0 = seg * SEGLEN, t1 = min(NBIN, t0 + SEGLEN);
        for (int t = t0 + tid; t < t1; t += 256) {
            int I = (int)((147.0f - sqrtf(147.0f * 147.0f - 8.0f * (float)t)) * 0.5f);
            I = max(0, min(72, I));
            while (I > 0 && (I * 73 - (I * (I - 1)) / 2) > t) I--;
            while (I < 72 && ((I + 1) * 73 - ((I + 1) * I) / 2) <= t) I++;
            int J = I + 1 + (t - (I * 73 - (I * (I - 1)) / 2));
            // [bpair][head][bin-parity]
            g_wA2[(t >> 1) * 128 + h * 2 + (t & 1)] =
                (w[I * FMD + J] - w[J * FMD + I]) * (1.0f / 16.0f);
            if (h == 0) g_binIJ[t] = (unsigned short)((I << 8) | J);
        }
    } else {
        int h = blk - NHEAD * SEGS;
        const float* src = wDI + h * FMD * FMD;
        for (int i = tid; i < FMD * FMD; i += 256) w[i] = src[i];
        __syncthreads();
        if (tid < FMD) {
            float cs = 0.f, rs = 0.f;
            #pragma unroll 2
            for (int I = 0; I < FMD; I++) {
                cs += w[I * FMD + tid];
                rs += w[tid * FMD + I];
            }
            g_wDIeff[tid * NHEAD + h] = (cs - rs) * 0.25f;
        }
    }
}

// ---------------- fused: on-the-fly pool + contraction + MLP tail ----------------
struct TailS {
    float hN[RB][NHEAD];
    float hD[RB][NHEAD];
    float emb[RB][2 * NEMB];
    float z1[RB][NEMB];
    float z2[RB][20];
};
union BigU {
    struct {
        float xe[RB][XPAD];        // 9600 B, conflict-free rows
        float ps3[2][64][16];      // 8192 B: [buf][bpair][row*2+parity]
    } a;
    unsigned long long redu[4][RB][32];   // 4096 B slot-reduction (slot, row, head-pair)
    float redf[4][RB][NHEAD];             // float view
};

__global__ __launch_bounds__(512, 2) void fused_kernel(
    const float* __restrict__ x,
    const float* __restrict__ bDI,   const float* __restrict__ fcDI_w,  const float* __restrict__ fcDI_b,
    const float* __restrict__ bNDI,  const float* __restrict__ fcNDI_w, const float* __restrict__ fcNDI_b,
    const float* __restrict__ fc1_w, const float* __restrict__ fc1_b,
    const float* __restrict__ l1_w,  const float* __restrict__ l1_b,
    const float* __restrict__ l2_w,  const float* __restrict__ l2_b,
    float* __restrict__ out)
{
    __shared__ BigU u;
    __shared__ TailS t;
    __shared__ float sus[RB][FMD];
    __shared__ unsigned short sIJ[NBINP];

    int tid  = threadIdx.x;
    int row0 = blockIdx.x * RB;

    // consumer mapping: 32 head-pairs x 4 bpair-slots x 4 row-groups (2 rows each)
    int hp   = tid & 31;          // heads 2hp, 2hp+1
    int slot = (tid >> 5) & 3;    // 16 consecutive bpairs per slot
    int rgrp = tid >> 7;          // 0..3, rows 2*rgrp, 2*rgrp+1

    // stage 0: LUT (zero-padded) + x rows (+eps/2 folded in)
    for (int i = tid; i < NBINP; i += 512) sIJ[i] = (i < NBIN) ? g_binIJ[i] : (unsigned short)0;
    for (int i = tid; i < RB * NW; i += 512) {
        int r = i / NW, c = i % NW;
        u.a.xe[r][c] = x[(size_t)(row0 + r) * 300 + c] + 5e-6f;
    }
    __syncthreads();
    // group sums — RB*FMD = 592 > 512: strided loop required
    for (int i = tid; i < RB * FMD; i += 512) {
        int r = i / FMD, K = i % FMD;
        float4 v = ((const float4*)u.a.xe[r])[K];
        sus[r][K] = v.x + v.y + v.z + v.w;
    }

    // ---- pooled-NDI producer: one 128-bin chunk -> ps3[buf][bpair][r*2+par]
    // 4 fractions share one denominator: 4 rcp per bin
    #define STAGE1(C0, BUF)                                                         \
    {                                                                               \
        _Pragma("unroll")                                                           \
        for (int it = 0; it < 2; it++) {                                            \
            int idx = tid + it * 512;                                               \
            int r = idx & 7, b = idx >> 3;                                          \
            unsigned ij = sIJ[(C0) + b];                                            \
            const float4* xs4 = (const float4*)u.a.xe[r];                           \
            float4 ga = xs4[ij >> 8];                                               \
            float4 gb = xs4[ij & 255];                                              \
            float av[4] = {ga.x, ga.y, ga.z, ga.w};                                 \
            float bv[4] = {gb.x, gb.y, gb.z, gb.w};                                 \
            float acc = 0.f;                                                        \
            _Pragma("unroll")                                                       \
            for (int j = 0; j < 4; j++) {                                           \
                float xj = bv[j];                                                   \
                float s0 = av[0] + xj, d0 = xj - av[0];                             \
                float s1 = av[1] + xj, d1 = xj - av[1];                             \
                float s2 = av[2] + xj, d2 = xj - av[2];                             \
                float s3 = av[3] + xj, d3 = xj - av[3];                             \
                float t01 = s0 * s1, t23 = s2 * s3;                                 \
                float n01 = fmaf(d0, s1, d1 * s0);                                  \
                float n23 = fmaf(d2, s3, d3 * s2);                                  \
                float num = fmaf(n01, t23, n23 * t01);                              \
                float den = t01 * t23;                                              \
                float y;                                                            \
                asm("rcp.approx.f32 %0, %1;" : "=f"(y) : "f"(den));                 \
                acc = fmaf(num, y, acc);                                            \
            }                                                                       \
            u.a.ps3[BUF][b >> 1][(r << 1) | (b & 1)] = acc;                         \
        }                                                                           \
    }

    // accs: bins packed in f32x2 lanes; [head][row]
    unsigned long long a00 = 0ull, a01 = 0ull, a10 = 0ull, a11 = 0ull;

    STAGE1(0, 0);
    __syncthreads();
    for (int c = 0; c < NCHUNK; c++) {
        int buf = c & 1;
        int c0 = c << 7;
        if (c < NCHUNK - 1) STAGE1(c0 + 128, buf ^ 1);
        // consumer: 16 bpairs/thread; LDG.128 w = {b0h0,b1h0,b0h1,b1h1}; LDS.128 p broadcast
        const float* wp = g_wA2 + ((size_t)(c0 >> 1) + 16 * slot) * 128 + 4 * hp;
        const ulonglong2* pp = (const ulonglong2*)&u.a.ps3[buf][16 * slot][4 * rgrp];
        #pragma unroll
        for (int i = 0; i < 16; i++) {
            ulonglong2 w = *(const ulonglong2*)(wp + (size_t)i * 128);
            ulonglong2 p = pp[(size_t)i * 4];   // bpair stride = 16 floats = 4 ulonglong2
            ffma2(a00, p.x, w.x);   // row 2rgrp,   head 2hp
            ffma2(a01, p.x, w.y);   // row 2rgrp,   head 2hp+1
            ffma2(a10, p.y, w.x);   // row 2rgrp+1, head 2hp
            ffma2(a11, p.y, w.y);   // row 2rgrp+1, head 2hp+1
        }
        __syncthreads();
    }

    // ---- fold bin-parity lanes, reduce 4 slots via aliased smem (xe/ps3 dead now)
    {
        float lo, hi;
        float s00, s01, s10, s11;
        upk2(lo, hi, a00); s00 = lo + hi;
        upk2(lo, hi, a01); s01 = lo + hi;
        upk2(lo, hi, a10); s10 = lo + hi;
        upk2(lo, hi, a11); s11 = lo + hi;
        int r0 = 2 * rgrp;
        u.redu[slot][r0 + 0][hp] = pk2(s00, s01);   // heads 2hp,2hp+1 adjacent
        u.redu[slot][r0 + 1][hp] = pk2(s10, s11);
    }
    __syncthreads();

    // one thread per (row, head): NDI reduce + bias + elu; DI head full dot
    {
        int r = tid >> 6, h = tid & 63;
        float s = u.redf[0][r][h] + u.redf[1][r][h] + u.redf[2][r][h] + u.redf[3][r][h];
        t.hN[r][h] = elu1(s + bNDI[h]);

        float d = 0.f;
        #pragma unroll 2
        for (int K = 0; K < FMD; K++)
            d = fmaf(sus[r][K], g_wDIeff[K * NHEAD + h], d);
        t.hD[r][h] = elu1(d + bDI[h]);
    }
    __syncthreads();

    // eDI / eNDI (48 each) -> emb[96]
    if (tid < RB * NEMB) {
        int r = tid / NEMB, e = tid % NEMB;
        float v = fcDI_b[e], v2 = fcNDI_b[e];
        #pragma unroll 8
        for (int h = 0; h < NHEAD; h++) {
            v  = fmaf(fcDI_w[e * NHEAD + h],  t.hD[r][h], v);
            v2 = fmaf(fcNDI_w[e * NHEAD + h], t.hN[r][h], v2);
        }
        t.emb[r][e]        = elu1(v);
        t.emb[r][NEMB + e] = elu1(v2);
    }
    __syncthreads();

    // fc1: 96 -> 48
    if (tid < RB * NEMB) {
        int r = tid / NEMB, o = tid % NEMB;
        float v = fc1_b[o];
        #pragma unroll 8
        for (int c = 0; c < 2 * NEMB; c++) v = fmaf(fc1_w[o * 2 * NEMB + c], t.emb[r][c], v);
        t.z1[r][o] = elu1(v);
    }
    __syncthreads();

    // l1: 48 -> 20
    if (tid < RB * 20) {
        int r = tid / 20, o = tid % 20;
        float v = l1_b[o];
        #pragma unroll 8
        for (int c = 0; c < NEMB; c++) v = fmaf(l1_w[o * NEMB + c], t.z1[r][c], v);
        t.z2[r][o] = elu1(v);
    }
    __syncthreads();

    // l2: 20 -> 1, sigmoid
    if (tid < RB) {
        float v = l2_b[0];
        #pragma unroll
        for (int c = 0; c < 20; c++) v = fmaf(l2_w[c], t.z2[tid][c], v);
        out[row0 + tid] = 1.0f / (1.0f + expf(-v));
    }
}

extern "C" void kernel_launch(void* const* d_in, const int* in_sizes, int n_in,
                              void* d_out, int out_size) {
    const float* x       = (const float*)d_in[0];
    const float* wDI     = (const float*)d_in[1];
    const float* bDI     = (const float*)d_in[2];
    const float* fcDI_w  = (const float*)d_in[3];
    const float* fcDI_b  = (const float*)d_in[4];
    const float* wNDI    = (const float*)d_in[5];
    const float* bNDI    = (const float*)d_in[6];
    const float* fcNDI_w = (const float*)d_in[7];
    const float* fcNDI_b = (const float*)d_in[8];
    const float* fc1_w   = (const float*)d_in[9];
    const float* fc1_b   = (const float*)d_in[10];
    const float* l1_w    = (const float*)d_in[11];
    const float* l1_b    = (const float*)d_in[12];
    const float* l2_w    = (const float*)d_in[13];
    const float* l2_b    = (const float*)d_in[14];
    float* out = (float*)d_out;

    int B = in_sizes[0] / 300;   // 2048

    prep_kernel<<<NHEAD * SEGS + NHEAD, 256>>>(wDI, wNDI);
    fused_kernel<<<B / RB, 512>>>(x, bDI, fcDI_w, fcDI_b, bNDI, fcNDI_w, fcNDI_b,
                                  fc1_w, fc1_b, l1_w, l1_b, l2_w, l2_b, out);
}